// round 12
// baseline (speedup 1.0000x reference)
#include <cuda_runtime.h>
#include <stdint.h>

#define BB 64
#define NN 68
#define ZZ 384
#define MM 46
#define DC 7
#define EE (MM*DC)   /* 322 */
#define NITER 10
#define MAXDEG 46

#define CT 96        /* check threads per check: each owns 4 z (one u32) */
#define CM 2         /* checks per CTA */
#define WX 12        /* writer CTAs appended to check grid */
#define WZ 32        /* z rows per writer CTA (12*32 = 384) */

// prev: check-node output messages, VAR-aligned rows: g_prev[b][e][z]
__device__ __align__(128) int8_t g_prev[BB * EE * ZZ];   // ~7.9 MB
// t16[b][n][z] = 16 * (xa + msg_sum/16)  (out = t16/16; check input = t16 - c)
__device__ __align__(16)  float  g_t16[BB * NN * ZZ];    // ~6.7 MB
// CSR: variable -> incident edge row offsets (e * ZZ)
__device__ int g_var_deg[NN];
__device__ int g_var_off[NN * MAXDEG];

// ---------------------------------------------------------------------------
// CSR setup (atomic scatter; order-independent because sums are integer-exact)
// ---------------------------------------------------------------------------
__global__ void setup_csr(const int* __restrict__ etv) {
    const int t = threadIdx.x;
    if (t < NN) g_var_deg[t] = 0;
    __syncthreads();
    if (t < EE) {
        const int n = etv[t];
        const int slot = atomicAdd(&g_var_deg[n], 1);
        g_var_off[n * MAXDEG + slot] = t * ZZ;
    }
}

// ---------------------------------------------------------------------------
// Out-writer work unit: out[b][z0..z0+31][:] = t16[b][:][z0..z0+31] / 16
// (192-thread CTA; smem transpose; streaming stores)
// ---------------------------------------------------------------------------
__device__ __forceinline__ void write_out_part(int wb, int b,
                                               float* __restrict__ out_slice,
                                               int tid) {
    __shared__ float tile[NN][WZ + 1];
    const int z0 = wb * WZ;
    const float* __restrict__ tp = g_t16 + (size_t)b * NN * ZZ + z0;

    for (int idx = tid; idx < NN * (WZ / 4); idx += CT * CM) {
        const int n  = idx >> 3;        // WZ/4 = 8
        const int zc = idx & 7;
        const float4 v = *(const float4*)(tp + (size_t)n * ZZ + 4 * zc);
        tile[n][4 * zc + 0] = v.x * 0.0625f;
        tile[n][4 * zc + 1] = v.y * 0.0625f;
        tile[n][4 * zc + 2] = v.z * 0.0625f;
        tile[n][4 * zc + 3] = v.w * 0.0625f;
    }
    __syncthreads();

    float* __restrict__ op = out_slice + (size_t)(b * ZZ + z0) * NN;
    for (int idx = tid; idx < WZ * (NN / 4); idx += CT * CM) {
        const int zl = idx / 17;
        const int nq = idx - zl * 17;
        float4 v;
        v.x = tile[4 * nq + 0][zl];
        v.y = tile[4 * nq + 1][zl];
        v.z = tile[4 * nq + 2][zl];
        v.w = tile[4 * nq + 3][zl];
        __stcs((float4*)(op + (size_t)zl * NN + 4 * nq), v);
    }
}

// ---------------------------------------------------------------------------
// Check kernel: quantizes its inputs inline from t16 (or xa on iter 0) and
// old prev, then int8 SIMD min-sum (4 z per thread in u32), writes new prev
// var-aligned via smem staging. Grid.x = MM/CM (+WX writer CTAs when !FIRST;
// writer CTAs stream out[it-1] from the same t16 buffer -> overlap, no race).
// ---------------------------------------------------------------------------
template <bool FIRST>
__global__ void __launch_bounds__(CT * CM)
check_kernel(const int*   __restrict__ shift,
             const int*   __restrict__ etv,
             const float* __restrict__ cnw,
             const float* __restrict__ xa,
             float* __restrict__ out_prev,
             int it) {
    const int bxx = blockIdx.x;
    const int b   = blockIdx.y;
    const int tid = threadIdx.y * CT + threadIdx.x;

    if (bxx >= MM / CM) {                 // ---- fused out-writer CTA ----
        if (!FIRST) write_out_part(bxx - MM / CM, b, out_prev, tid);
        return;
    }

    const int m  = bxx * CM + threadIdx.y;
    const int t  = threadIdx.x;
    const int ty = threadIdx.y;

    __shared__ uint8_t  lutb[32];
    __shared__ uint32_t stage[CM][DC][CT];
    if (ty == 0 && t < 32) {
        const float w = cnw[it];
        lutb[t] = (uint8_t)(int)fminf(rintf(w * (float)t), 31.0f);
    }
    __syncthreads();

    const int mbase = m * DC;
    const float* __restrict__ srcbase = FIRST ? xa : g_t16;

    int b0[DC];
    uint32_t c[DC];
#pragma unroll
    for (int j = 0; j < DC; ++j) {
        const int e = mbase + j;
        const int s = __ldg(shift + e);
        const int n = __ldg(etv + e);
        int byte0 = 4 * t + s;
        if (byte0 >= ZZ) byte0 -= ZZ;
        b0[j] = byte0;

        const float* __restrict__ rp = srcbase + (size_t)(b * NN + n) * ZZ;
        int z = byte0;
        const float v0 = __ldg(rp + z); if (++z == ZZ) z = 0;
        const float v1 = __ldg(rp + z); if (++z == ZZ) z = 0;
        const float v2 = __ldg(rp + z); if (++z == ZZ) z = 0;
        const float v3 = __ldg(rp + z);

        float x0, x1, x2, x3;
        if (FIRST) {
            x0 = 16.0f * v0; x1 = 16.0f * v1; x2 = 16.0f * v2; x3 = 16.0f * v3;
        } else {
            const uint32_t* pp = (const uint32_t*)
                (g_prev + (size_t)(b * EE + e) * ZZ);
            const int i0 = byte0 >> 2;
            int i1 = i0 + 1;
            if (i1 == ZZ / 4) i1 = 0;
            const uint32_t cp = __funnelshift_r(pp[i0], pp[i1], (byte0 & 3) * 8);
            x0 = v0 - (float)(int)(int8_t)(cp);
            x1 = v1 - (float)(int)(int8_t)(cp >> 8);
            x2 = v2 - (float)(int)(int8_t)(cp >> 16);
            x3 = v3 - (float)(int)(int8_t)(cp >> 24);
        }
        const int k0 = max(-31, min(31, __float2int_rn(x0)));
        const int k1 = max(-31, min(31, __float2int_rn(x1)));
        const int k2 = max(-31, min(31, __float2int_rn(x2)));
        const int k3 = max(-31, min(31, __float2int_rn(x3)));
        const uint32_t p1 = __byte_perm((uint32_t)k0, (uint32_t)k1, 0x0040);
        const uint32_t p2 = __byte_perm((uint32_t)k2, (uint32_t)k3, 0x0040);
        c[j] = __byte_perm(p1, p2, 0x5410);
    }

    uint32_t a[DC];
#pragma unroll
    for (int j = 0; j < DC; ++j) a[j] = __vabs4(c[j]);
    uint32_t m1 = a[0];
#pragma unroll
    for (int j = 1; j < DC; ++j) m1 = __vminu4(m1, a[j]);

    uint32_t eq[DC], cnt = 0, m2 = 0xFFFFFFFFu;
#pragma unroll
    for (int j = 0; j < DC; ++j) {
        eq[j] = __vcmpeq4(a[j], m1);
        cnt  += eq[j] & 0x01010101u;
        m2    = __vminu4(m2, a[j] | eq[j]);
    }
    const uint32_t unique = __vcmpeq4(cnt, 0x01010101u);
    m2 = __vminu4(m2, 0x1F1F1F1Fu);

    uint32_t tot = c[0];
#pragma unroll
    for (int j = 1; j < DC; ++j) tot ^= c[j];

    const uint32_t q1 =  (uint32_t)lutb[ m1        & 31]
                      | ((uint32_t)lutb[(m1 >> 8)  & 31] << 8)
                      | ((uint32_t)lutb[(m1 >> 16) & 31] << 16)
                      | ((uint32_t)lutb[(m1 >> 24) & 31] << 24);
    const uint32_t q2 =  (uint32_t)lutb[ m2        & 31]
                      | ((uint32_t)lutb[(m2 >> 8)  & 31] << 8)
                      | ((uint32_t)lutb[(m2 >> 16) & 31] << 16)
                      | ((uint32_t)lutb[(m2 >> 24) & 31] << 24);

#pragma unroll
    for (int j = 0; j < DC; ++j) {
        const uint32_t sel  = eq[j] & unique;
        const uint32_t q    = (q2 & sel) | (q1 & ~sel);
        const uint32_t nm   = __vcmpgts4(0u, tot ^ c[j]);
        const uint32_t outw = __vsub4(q ^ nm, nm);
        uint8_t* s8 = (uint8_t*)stage[ty][j];
#pragma unroll
        for (int k = 0; k < 4; ++k) {
            int bk = b0[j] + k;
            if (bk >= ZZ) bk -= ZZ;
            s8[bk] = (uint8_t)(outw >> (8 * k));
        }
    }
    __syncthreads();

    int8_t* __restrict__ pv = g_prev + (size_t)(b * EE + mbase) * ZZ + 4 * t;
#pragma unroll
    for (int j = 0; j < DC; ++j)
        *(uint32_t*)(pv + j * ZZ) = stage[ty][j][t];
}

// ---------------------------------------------------------------------------
// Variable core: shift-free, no emit, no out. Block 128 = 32 z-u32 lanes x 4
// n (one n per warp). Grid (3, 17, B). Sum prev (xor-bias, exact) + xa ->
// t16 float4 store. That's it.
// ---------------------------------------------------------------------------
__global__ void __launch_bounds__(128)
var_kernel(const float* __restrict__ xa) {
    const int b   = blockIdx.z;
    const int n   = blockIdx.y * 4 + (threadIdx.x >> 5);
    const int tx  = threadIdx.x & 31;
    const int zb  = 4 * (blockIdx.x * 32 + tx);
    const int bbase = b * EE * ZZ;

    const float4 xv = __ldg((const float4*)(xa + (size_t)(b * NN + n) * ZZ + zb));

    const int d = g_var_deg[n];
    const int* __restrict__ ol = &g_var_off[n * MAXDEG];

    uint32_t accE = 0, accO = 0;            // (byte ^ 0x80) sums in 16-bit lanes
    for (int i = 0; i < d; ++i) {
        const uint32_t c = *(const uint32_t*)(g_prev + bbase + ol[i] + zb)
                         ^ 0x80808080u;
        accE += c & 0x00FF00FFu;
        accO += (c >> 8) & 0x00FF00FFu;
    }
    const int bias = d << 7;
    float4 tv;
    tv.x = fmaf(xv.x, 16.0f, (float)((int)(accE & 0xFFFFu) - bias));
    tv.y = fmaf(xv.y, 16.0f, (float)((int)(accO & 0xFFFFu) - bias));
    tv.z = fmaf(xv.z, 16.0f, (float)((int)(accE >> 16)     - bias));
    tv.w = fmaf(xv.w, 16.0f, (float)((int)(accO >> 16)     - bias));

    *(float4*)(g_t16 + (size_t)(b * NN + n) * ZZ + zb) = tv;
}

// ---------------------------------------------------------------------------
// Standalone writer for the final iteration's output slice.
// ---------------------------------------------------------------------------
__global__ void __launch_bounds__(CT * CM)
out_writer(float* __restrict__ out_slice) {
    write_out_part(blockIdx.x, blockIdx.y,
                   out_slice, threadIdx.y * CT + threadIdx.x);
}

// ---------------------------------------------------------------------------
// Launch
// ---------------------------------------------------------------------------
extern "C" void kernel_launch(void* const* d_in, const int* in_sizes, int n_in,
                              void* d_out, int out_size) {
    const float* xa    = (const float*)d_in[0];   // (B, N, Z) f32
    const float* cnw   = (const float*)d_in[1];   // (ITERS,) f32
    const int*   etv   = (const int*)d_in[2];     // (E,) i32
    // d_in[3] = edge_to_check — grouping is implicit (repeat(arange(M), 7))
    const int*   shift = (const int*)d_in[4];     // (E,) i32
    float* out = (float*)d_out;                   // (ITERS, B, Z, N) f32

    setup_csr<<<1, EE>>>(etv);

    const dim3 cblock(CT, CM);
    const dim3 vgrid(3, 17, BB);
    const size_t slice = (size_t)BB * ZZ * NN;

    for (int it = 0; it < NITER; ++it) {
        if (it == 0) {
            check_kernel<true><<<dim3(MM / CM, BB), cblock>>>(
                shift, etv, cnw, xa, nullptr, it);
        } else {
            check_kernel<false><<<dim3(MM / CM + WX, BB), cblock>>>(
                shift, etv, cnw, xa, out + (size_t)(it - 1) * slice, it);
        }
        var_kernel<<<vgrid, 128>>>(xa);
    }
    out_writer<<<dim3(WX, BB), cblock>>>(out + (size_t)(NITER - 1) * slice);
}

// round 14
// speedup vs baseline: 1.0470x; 1.0470x over previous
#include <cuda_runtime.h>
#include <stdint.h>

#define BB 64
#define NN 68
#define ZZ 384
#define MM 46
#define DC 7
#define EE (MM*DC)   /* 322 */
#define NITER 10
#define MAXDEG 46
#define RCAP 12      /* register-cached edges per var thread */

#define CT 96        /* check threads per check: each owns 4 z (one u32) */
#define CM 2         /* checks per CTA */

// prev: check-node output messages, VAR-aligned rows: g_prev[b][e][z]
// (check kernel applies the edge shift at store time via smem staging)
__device__ __align__(128) int8_t g_prev[BB * EE * ZZ];   // ~7.9 MB
// x2: quantized check inputs, VAR-aligned rows:         g_x2[b][e][z]
__device__ __align__(128) int8_t g_x2[BB * EE * ZZ];     // ~7.9 MB
// CSR: variable -> incident edge row offsets (e * ZZ)
__device__ int g_var_deg[NN];
__device__ int g_var_off[NN * MAXDEG];

// ---------------------------------------------------------------------------
// CSR setup (atomic scatter; order-independent because sums are integer-exact)
// ---------------------------------------------------------------------------
__global__ void setup_csr(const int* __restrict__ etv) {
    const int t = threadIdx.x;
    if (t < NN) g_var_deg[t] = 0;
    __syncthreads();
    if (t < EE) {
        const int n = etv[t];
        const int slot = atomicAdd(&g_var_deg[n], 1);
        g_var_off[n * MAXDEG + slot] = t * ZZ;
    }
}

// quantize value scaled by 16: code = sign(d) * min(rint(|d|), 31), as byte
__device__ __forceinline__ uint32_t qbyte(float d) {
    const float q = fminf(rintf(fabsf(d)), 31.0f);
    const int c = (int)(d < 0.0f ? -q : q);
    return (uint32_t)c & 0xFFu;
}

// ---------------------------------------------------------------------------
// Initial x2(0) = Q(xa) codes, var-aligned. Grid (E, B) x 96 threads.
// ---------------------------------------------------------------------------
__global__ void __launch_bounds__(CT)
init_x2(const float* __restrict__ xa, const int* __restrict__ etv) {
    const int e = blockIdx.x;
    const int b = blockIdx.y;
    const int t = threadIdx.x;
    const int v = etv[e];
    const float4 xv = *(const float4*)(xa + (size_t)(b * NN + v) * ZZ + 4 * t);
    const uint32_t w = qbyte(xv.x * 16.0f)
                     | (qbyte(xv.y * 16.0f) << 8)
                     | (qbyte(xv.z * 16.0f) << 16)
                     | (qbyte(xv.w * 16.0f) << 24);
    *(uint32_t*)(g_x2 + (size_t)(b * EE + e) * ZZ + 4 * t) = w;
}

// ---------------------------------------------------------------------------
// Check kernel: int8 SIMD min-sum, 4 z per thread packed in u32.
// Reads x2 var-aligned (funnel shift by edge shift s, index b0 = 4t+s).
// Writes prev VAR-ALIGNED: rotated message bytes staged in smem (each byte
// written exactly once -> race-free), then copied out as aligned u32.
// ---------------------------------------------------------------------------
__global__ void __launch_bounds__(CT * CM)
check_kernel(const int* __restrict__ shift,
             const float* __restrict__ cnw,
             int it) {
    const int m  = blockIdx.x * CM + threadIdx.y;
    const int b  = blockIdx.y;
    const int t  = threadIdx.x;
    const int ty = threadIdx.y;

    __shared__ uint8_t  lutb[32];
    __shared__ uint32_t stage[CM][DC][CT];   // rotated message rows (384B each)
    if (ty == 0 && t < 32) {
        const float w = cnw[it];
        lutb[t] = (uint8_t)(int)fminf(rintf(w * (float)t), 31.0f);
    }
    __syncthreads();

    const int8_t* __restrict__ xb = g_x2 + (size_t)(b * EE + m * DC) * ZZ;

    int b0[DC];
    uint32_t c[DC];
#pragma unroll
    for (int j = 0; j < DC; ++j) {
        const int s = shift[m * DC + j];
        int byte0 = 4 * t + s;
        if (byte0 >= ZZ) byte0 -= ZZ;
        b0[j] = byte0;
        const int i0 = byte0 >> 2;
        int i1 = i0 + 1;
        if (i1 == ZZ / 4) i1 = 0;
        const uint32_t* p = (const uint32_t*)(xb + j * ZZ);
        c[j] = __funnelshift_r(p[i0], p[i1], (byte0 & 3) * 8);
    }

    uint32_t a[DC];
#pragma unroll
    for (int j = 0; j < DC; ++j) a[j] = __vabs4(c[j]);
    uint32_t m1 = a[0];
#pragma unroll
    for (int j = 1; j < DC; ++j) m1 = __vminu4(m1, a[j]);

    uint32_t eq[DC], cnt = 0, m2 = 0xFFFFFFFFu;
#pragma unroll
    for (int j = 0; j < DC; ++j) {
        eq[j] = __vcmpeq4(a[j], m1);
        cnt  += eq[j] & 0x01010101u;
        m2    = __vminu4(m2, a[j] | eq[j]);
    }
    const uint32_t unique = __vcmpeq4(cnt, 0x01010101u);
    m2 = __vminu4(m2, 0x1F1F1F1Fu);

    uint32_t tot = c[0];
#pragma unroll
    for (int j = 1; j < DC; ++j) tot ^= c[j];

    const uint32_t q1 =  (uint32_t)lutb[ m1        & 31]
                      | ((uint32_t)lutb[(m1 >> 8)  & 31] << 8)
                      | ((uint32_t)lutb[(m1 >> 16) & 31] << 16)
                      | ((uint32_t)lutb[(m1 >> 24) & 31] << 24);
    const uint32_t q2 =  (uint32_t)lutb[ m2        & 31]
                      | ((uint32_t)lutb[(m2 >> 8)  & 31] << 8)
                      | ((uint32_t)lutb[(m2 >> 16) & 31] << 16)
                      | ((uint32_t)lutb[(m2 >> 24) & 31] << 24);

#pragma unroll
    for (int j = 0; j < DC; ++j) {
        const uint32_t sel  = eq[j] & unique;
        const uint32_t q    = (q2 & sel) | (q1 & ~sel);
        const uint32_t nm   = __vcmpgts4(0u, tot ^ c[j]);
        const uint32_t outw = __vsub4(q ^ nm, nm);
        uint8_t* s8 = (uint8_t*)stage[ty][j];
#pragma unroll
        for (int k = 0; k < 4; ++k) {
            int bk = b0[j] + k;
            if (bk >= ZZ) bk -= ZZ;
            s8[bk] = (uint8_t)(outw >> (8 * k));
        }
    }
    __syncthreads();

    int8_t* __restrict__ pv = g_prev + (size_t)(b * EE + m * DC) * ZZ + 4 * t;
#pragma unroll
    for (int j = 0; j < DC; ++j)
        *(uint32_t*)(pv + j * ZZ) = stage[ty][j][t];
}

// ---------------------------------------------------------------------------
// Variable kernel: shift-free. Block 128 = 32 z-u32 lanes x 4 n (one n per
// warp). Grid (3, 17, B). xa load hoisted to overlap DRAM latency with the
// prev sum loop. prev codes register-cached (RCAP slots, predicated unroll)
// so the emit pass does no reloads. out written with streaming stores.
// ---------------------------------------------------------------------------
template <bool EMIT>
__global__ void __launch_bounds__(128)
var_kernel(const float* __restrict__ xa, float* __restrict__ out_slice) {
    const int b   = blockIdx.z;
    const int n0  = blockIdx.y * 4;
    const int zu0 = blockIdx.x * 32;        // u32 units; z0 = 4*zu0
    const int tx  = threadIdx.x & 31;       // z u32 lane
    const int ty  = threadIdx.x >> 5;       // n within group
    const int zb  = 4 * (zu0 + tx);         // z byte index
    const int n   = n0 + ty;
    const int bbase = b * EE * ZZ;

    __shared__ float tile[4][132];

    // issue the (possibly DRAM) xa load FIRST so it overlaps the prev loads
    const float4 xv = __ldg((const float4*)(xa + (size_t)(b * NN + n) * ZZ + zb));

    const int d = g_var_deg[n];
    const int* __restrict__ ol = &g_var_off[n * MAXDEG];

    uint32_t cc[RCAP];                      // cached prev code words
    uint32_t accE = 0, accO = 0;            // (byte ^ 0x80) sums in 16-bit lanes
#pragma unroll
    for (int i = 0; i < RCAP; ++i) {
        if (i < d) {
            cc[i] = *(const uint32_t*)(g_prev + bbase + ol[i] + zb);
            const uint32_t c = cc[i] ^ 0x80808080u;
            accE += c & 0x00FF00FFu;        // bytes 0,2
            accO += (c >> 8) & 0x00FF00FFu; // bytes 1,3
        }
    }
    for (int i = RCAP; i < d; ++i) {        // correctness fallback (rare)
        const uint32_t c = *(const uint32_t*)(g_prev + bbase + ol[i] + zb)
                         ^ 0x80808080u;
        accE += c & 0x00FF00FFu;
        accO += (c >> 8) & 0x00FF00FFu;
    }
    const int bias = d << 7;                // 128 * d per lane
    const float s0 = (float)((int)(accE & 0xFFFFu) - bias);
    const float s1 = (float)((int)(accO & 0xFFFFu) - bias);
    const float s2 = (float)((int)(accE >> 16)     - bias);
    const float s3 = (float)((int)(accO >> 16)     - bias);

    const float t0 = fmaf(xv.x, 16.0f, s0);
    const float t1 = fmaf(xv.y, 16.0f, s1);
    const float t2 = fmaf(xv.z, 16.0f, s2);
    const float t3 = fmaf(xv.w, 16.0f, s3);

    float4 ov;
    ov.x = t0 * 0.0625f; ov.y = t1 * 0.0625f;
    ov.z = t2 * 0.0625f; ov.w = t3 * 0.0625f;
    *(float4*)&tile[ty][4 * tx] = ov;
    __syncthreads();

    // out [b][z][n0..n0+3]: one streaming float4 per thread (write-once data)
    {
        const int zl = threadIdx.x;         // 0..127
        float4 val;
        val.x = tile[0][zl];
        val.y = tile[1][zl];
        val.z = tile[2][zl];
        val.w = tile[3][zl];
        __stcs((float4*)(out_slice + (size_t)(b * ZZ + 4 * zu0 + zl) * NN + n0), val);
    }

    if (EMIT) {
        // pre-clamp so k fits int8; output-invariant (|t|>=63 -> code 31)
        const float tc0 = fminf(fmaxf(t0, -63.0f), 63.0f);
        const float tc1 = fminf(fmaxf(t1, -63.0f), 63.0f);
        const float tc2 = fminf(fmaxf(t2, -63.0f), 63.0f);
        const float tc3 = fminf(fmaxf(t3, -63.0f), 63.0f);
#pragma unroll
        for (int i = 0; i < RCAP; ++i) {
            if (i < d) {
                const uint32_t c = cc[i];   // from registers, no reload
                const int k0 = __float2int_rn(tc0 - (float)(int)(int8_t)(c));
                const int k1 = __float2int_rn(tc1 - (float)(int)(int8_t)(c >> 8));
                const int k2 = __float2int_rn(tc2 - (float)(int)(int8_t)(c >> 16));
                const int k3 = __float2int_rn(tc3 - (float)(int)(int8_t)(c >> 24));
                const uint32_t p1 = __byte_perm((uint32_t)k0, (uint32_t)k1, 0x0040);
                const uint32_t p2 = __byte_perm((uint32_t)k2, (uint32_t)k3, 0x0040);
                uint32_t pk = __byte_perm(p1, p2, 0x5410);
                pk = __vmins4(__vmaxs4(pk, 0xE1E1E1E1u), 0x1F1F1F1Fu);
                *(uint32_t*)(g_x2 + bbase + ol[i] + zb) = pk;
            }
        }
        for (int i = RCAP; i < d; ++i) {    // correctness fallback (rare)
            const int off = bbase + ol[i] + zb;
            const uint32_t c = *(const uint32_t*)(g_prev + off);
            const int k0 = __float2int_rn(tc0 - (float)(int)(int8_t)(c));
            const int k1 = __float2int_rn(tc1 - (float)(int)(int8_t)(c >> 8));
            const int k2 = __float2int_rn(tc2 - (float)(int)(int8_t)(c >> 16));
            const int k3 = __float2int_rn(tc3 - (float)(int)(int8_t)(c >> 24));
            const uint32_t p1 = __byte_perm((uint32_t)k0, (uint32_t)k1, 0x0040);
            const uint32_t p2 = __byte_perm((uint32_t)k2, (uint32_t)k3, 0x0040);
            uint32_t pk = __byte_perm(p1, p2, 0x5410);
            pk = __vmins4(__vmaxs4(pk, 0xE1E1E1E1u), 0x1F1F1F1Fu);
            *(uint32_t*)(g_x2 + off) = pk;
        }
    }
}

// ---------------------------------------------------------------------------
// Launch
// ---------------------------------------------------------------------------
extern "C" void kernel_launch(void* const* d_in, const int* in_sizes, int n_in,
                              void* d_out, int out_size) {
    const float* xa    = (const float*)d_in[0];   // (B, N, Z) f32
    const float* cnw   = (const float*)d_in[1];   // (ITERS,) f32
    const int*   etv   = (const int*)d_in[2];     // (E,) i32
    // d_in[3] = edge_to_check — grouping is implicit (repeat(arange(M), 7))
    const int*   shift = (const int*)d_in[4];     // (E,) i32
    float* out = (float*)d_out;                   // (ITERS, B, Z, N) f32

    setup_csr<<<1, EE>>>(etv);
    init_x2<<<dim3(EE, BB), CT>>>(xa, etv);

    const dim3 cgrid(MM / CM, BB);
    const dim3 cblock(CT, CM);
    const dim3 vgrid(3, 17, BB);
    const size_t slice = (size_t)BB * ZZ * NN;

    for (int it = 0; it < NITER; ++it) {
        check_kernel<<<cgrid, cblock>>>(shift, cnw, it);
        if (it < NITER - 1)
            var_kernel<true><<<vgrid, 128>>>(xa, out + (size_t)it * slice);
        else
            var_kernel<false><<<vgrid, 128>>>(xa, out + (size_t)it * slice);
    }
}

// round 15
// speedup vs baseline: 1.0815x; 1.0330x over previous
#include <cuda_runtime.h>
#include <stdint.h>

#define BB 64
#define NN 68
#define ZZ 384
#define MM 46
#define DC 7
#define EE (MM*DC)   /* 322 */
#define NITER 10

#define CT 96        /* check threads per check: each owns 4 z (one u32) */
#define CM 2         /* checks per CTA */

// prev / x2 rows are PERMUTED: edges of the same variable occupy contiguous
// rows. g_edge_row[e] maps a check-order edge to its row offset (x ZZ).
__device__ __align__(128) int8_t g_prev[BB * EE * ZZ];   // ~7.9 MB
__device__ __align__(128) int8_t g_x2[BB * EE * ZZ];     // ~7.9 MB
__device__ int g_var_deg[NN];
__device__ int g_var_start[NN];     // row start * ZZ
__device__ int g_edge_row[EE];      // permuted row * ZZ (check-order indexed)

// ---------------------------------------------------------------------------
// Setup: counting-sort edges by variable -> contiguous rows per variable.
// Slot order within a variable is atomic (nondeterministic) but the var sum
// is an exact integer add (commutative) -> output bit-identical.
// ---------------------------------------------------------------------------
__global__ void setup_csr(const int* __restrict__ etv) {
    __shared__ int cnt[NN], start[NN], slot[EE];
    const int t = threadIdx.x;
    if (t < NN) cnt[t] = 0;
    __syncthreads();
    if (t < EE) slot[t] = atomicAdd(&cnt[etv[t]], 1);
    __syncthreads();
    if (t == 0) {
        int acc = 0;
        for (int n = 0; n < NN; ++n) { start[n] = acc; acc += cnt[n]; }
    }
    __syncthreads();
    if (t < EE) g_edge_row[t] = (start[etv[t]] + slot[t]) * ZZ;
    if (t < NN) {
        g_var_deg[t]   = cnt[t];
        g_var_start[t] = start[t] * ZZ;
    }
}

// quantize value scaled by 16: code = sign(d) * min(rint(|d|), 31), as byte
__device__ __forceinline__ uint32_t qbyte(float d) {
    const float q = fminf(rintf(fabsf(d)), 31.0f);
    const int c = (int)(d < 0.0f ? -q : q);
    return (uint32_t)c & 0xFFu;
}

// ---------------------------------------------------------------------------
// Initial x2(0) = Q(xa) codes in permuted rows. Grid (E, B) x 96 threads.
// ---------------------------------------------------------------------------
__global__ void __launch_bounds__(CT)
init_x2(const float* __restrict__ xa, const int* __restrict__ etv) {
    const int e = blockIdx.x;
    const int b = blockIdx.y;
    const int t = threadIdx.x;
    const int v = etv[e];
    const float4 xv = *(const float4*)(xa + (size_t)(b * NN + v) * ZZ + 4 * t);
    const uint32_t w = qbyte(xv.x * 16.0f)
                     | (qbyte(xv.y * 16.0f) << 8)
                     | (qbyte(xv.z * 16.0f) << 16)
                     | (qbyte(xv.w * 16.0f) << 24);
    *(uint32_t*)(g_x2 + (size_t)(b * EE) * ZZ + g_edge_row[e] + 4 * t) = w;
}

// ---------------------------------------------------------------------------
// Check kernel: int8 SIMD min-sum, 4 z per thread packed in u32.
// Reads x2 from permuted rows (funnel shift by edge shift), writes prev to
// permuted rows via smem staging (rotation applied at store).
// ---------------------------------------------------------------------------
__global__ void __launch_bounds__(CT * CM)
check_kernel(const int* __restrict__ shift,
             const float* __restrict__ cnw,
             int it) {
    const int m  = blockIdx.x * CM + threadIdx.y;
    const int b  = blockIdx.y;
    const int t  = threadIdx.x;
    const int ty = threadIdx.y;

    __shared__ uint8_t  lutb[32];
    __shared__ uint32_t stage[CM][DC][CT];   // rotated message rows (384B each)
    if (ty == 0 && t < 32) {
        const float w = cnw[it];
        lutb[t] = (uint8_t)(int)fminf(rintf(w * (float)t), 31.0f);
    }
    __syncthreads();

    const size_t bbase = (size_t)(b * EE) * ZZ;

    int b0[DC], ro[DC];
    uint32_t c[DC];
#pragma unroll
    for (int j = 0; j < DC; ++j) {
        const int e = m * DC + j;
        const int s = __ldg(shift + e);
        ro[j] = __ldg(g_edge_row + e);
        int byte0 = 4 * t + s;
        if (byte0 >= ZZ) byte0 -= ZZ;
        b0[j] = byte0;
        const int i0 = byte0 >> 2;
        int i1 = i0 + 1;
        if (i1 == ZZ / 4) i1 = 0;
        const uint32_t* p = (const uint32_t*)(g_x2 + bbase + ro[j]);
        c[j] = __funnelshift_r(p[i0], p[i1], (byte0 & 3) * 8);
    }

    uint32_t a[DC];
#pragma unroll
    for (int j = 0; j < DC; ++j) a[j] = __vabs4(c[j]);
    uint32_t m1 = a[0];
#pragma unroll
    for (int j = 1; j < DC; ++j) m1 = __vminu4(m1, a[j]);

    uint32_t eq[DC], cnt = 0, m2 = 0xFFFFFFFFu;
#pragma unroll
    for (int j = 0; j < DC; ++j) {
        eq[j] = __vcmpeq4(a[j], m1);
        cnt  += eq[j] & 0x01010101u;
        m2    = __vminu4(m2, a[j] | eq[j]);
    }
    const uint32_t unique = __vcmpeq4(cnt, 0x01010101u);
    m2 = __vminu4(m2, 0x1F1F1F1Fu);

    uint32_t tot = c[0];
#pragma unroll
    for (int j = 1; j < DC; ++j) tot ^= c[j];

    const uint32_t q1 =  (uint32_t)lutb[ m1        & 31]
                      | ((uint32_t)lutb[(m1 >> 8)  & 31] << 8)
                      | ((uint32_t)lutb[(m1 >> 16) & 31] << 16)
                      | ((uint32_t)lutb[(m1 >> 24) & 31] << 24);
    const uint32_t q2 =  (uint32_t)lutb[ m2        & 31]
                      | ((uint32_t)lutb[(m2 >> 8)  & 31] << 8)
                      | ((uint32_t)lutb[(m2 >> 16) & 31] << 16)
                      | ((uint32_t)lutb[(m2 >> 24) & 31] << 24);

#pragma unroll
    for (int j = 0; j < DC; ++j) {
        const uint32_t sel  = eq[j] & unique;
        const uint32_t q    = (q2 & sel) | (q1 & ~sel);
        const uint32_t nm   = __vcmpgts4(0u, tot ^ c[j]);
        const uint32_t outw = __vsub4(q ^ nm, nm);
        uint8_t* s8 = (uint8_t*)stage[ty][j];
#pragma unroll
        for (int k = 0; k < 4; ++k) {
            int bk = b0[j] + k;
            if (bk >= ZZ) bk -= ZZ;
            s8[bk] = (uint8_t)(outw >> (8 * k));
        }
    }
    __syncthreads();

#pragma unroll
    for (int j = 0; j < DC; ++j)
        *(uint32_t*)(g_prev + bbase + ro[j] + 4 * t) = stage[ty][j][t];
}

// ---------------------------------------------------------------------------
// Variable kernel: index-free. Block 128 = 32 z-u32 lanes x 4 n (one n per
// warp). Grid (3, 17, B). Each var's prev/x2 rows are contiguous: addresses
// are base + i*ZZ + zb -> d independent LDGs, no index loads, no dependent
// address chain. xa load hoisted; out written with streaming stores.
// ---------------------------------------------------------------------------
template <bool EMIT>
__global__ void __launch_bounds__(128)
var_kernel(const float* __restrict__ xa, float* __restrict__ out_slice) {
    const int b   = blockIdx.z;
    const int n0  = blockIdx.y * 4;
    const int zu0 = blockIdx.x * 32;        // u32 units; z0 = 4*zu0
    const int tx  = threadIdx.x & 31;       // z u32 lane
    const int ty  = threadIdx.x >> 5;       // n within group
    const int zb  = 4 * (zu0 + tx);         // z byte index
    const int n   = n0 + ty;

    __shared__ float tile[4][132];

    // issue the (possibly DRAM) xa load FIRST so it overlaps the prev loads
    const float4 xv = __ldg((const float4*)(xa + (size_t)(b * NN + n) * ZZ + zb));

    const int d = g_var_deg[n];
    const int8_t* __restrict__ pb =
        g_prev + (size_t)(b * EE) * ZZ + g_var_start[n] + zb;

    uint32_t accE = 0, accO = 0;            // (byte ^ 0x80) sums in 16-bit lanes
    for (int i = 0; i < d; ++i) {
        const uint32_t c = *(const uint32_t*)(pb + i * ZZ) ^ 0x80808080u;
        accE += c & 0x00FF00FFu;            // bytes 0,2
        accO += (c >> 8) & 0x00FF00FFu;     // bytes 1,3
    }
    const int bias = d << 7;                // 128 * d per lane
    const float s0 = (float)((int)(accE & 0xFFFFu) - bias);
    const float s1 = (float)((int)(accO & 0xFFFFu) - bias);
    const float s2 = (float)((int)(accE >> 16)     - bias);
    const float s3 = (float)((int)(accO >> 16)     - bias);

    const float t0 = fmaf(xv.x, 16.0f, s0);
    const float t1 = fmaf(xv.y, 16.0f, s1);
    const float t2 = fmaf(xv.z, 16.0f, s2);
    const float t3 = fmaf(xv.w, 16.0f, s3);

    float4 ov;
    ov.x = t0 * 0.0625f; ov.y = t1 * 0.0625f;
    ov.z = t2 * 0.0625f; ov.w = t3 * 0.0625f;
    *(float4*)&tile[ty][4 * tx] = ov;
    __syncthreads();

    // out [b][z][n0..n0+3]: one streaming float4 per thread (write-once data)
    {
        const int zl = threadIdx.x;         // 0..127
        float4 val;
        val.x = tile[0][zl];
        val.y = tile[1][zl];
        val.z = tile[2][zl];
        val.w = tile[3][zl];
        __stcs((float4*)(out_slice + (size_t)(b * ZZ + 4 * zu0 + zl) * NN + n0), val);
    }

    if (EMIT) {
        int8_t* __restrict__ xb =
            g_x2 + (size_t)(b * EE) * ZZ + g_var_start[n] + zb;
        // pre-clamp so k fits int8; output-invariant (|t|>=63 -> code 31)
        const float tc0 = fminf(fmaxf(t0, -63.0f), 63.0f);
        const float tc1 = fminf(fmaxf(t1, -63.0f), 63.0f);
        const float tc2 = fminf(fmaxf(t2, -63.0f), 63.0f);
        const float tc3 = fminf(fmaxf(t3, -63.0f), 63.0f);
        for (int i = 0; i < d; ++i) {
            const uint32_t c = *(const uint32_t*)(pb + i * ZZ);   // L1 hit
            const int k0 = __float2int_rn(tc0 - (float)(int)(int8_t)(c));
            const int k1 = __float2int_rn(tc1 - (float)(int)(int8_t)(c >> 8));
            const int k2 = __float2int_rn(tc2 - (float)(int)(int8_t)(c >> 16));
            const int k3 = __float2int_rn(tc3 - (float)(int)(int8_t)(c >> 24));
            const uint32_t p1 = __byte_perm((uint32_t)k0, (uint32_t)k1, 0x0040);
            const uint32_t p2 = __byte_perm((uint32_t)k2, (uint32_t)k3, 0x0040);
            uint32_t pk = __byte_perm(p1, p2, 0x5410);
            pk = __vmins4(__vmaxs4(pk, 0xE1E1E1E1u), 0x1F1F1F1Fu);
            *(uint32_t*)(xb + i * ZZ) = pk;
        }
    }
}

// ---------------------------------------------------------------------------
// Launch
// ---------------------------------------------------------------------------
extern "C" void kernel_launch(void* const* d_in, const int* in_sizes, int n_in,
                              void* d_out, int out_size) {
    const float* xa    = (const float*)d_in[0];   // (B, N, Z) f32
    const float* cnw   = (const float*)d_in[1];   // (ITERS,) f32
    const int*   etv   = (const int*)d_in[2];     // (E,) i32
    // d_in[3] = edge_to_check — grouping is implicit (repeat(arange(M), 7))
    const int*   shift = (const int*)d_in[4];     // (E,) i32
    float* out = (float*)d_out;                   // (ITERS, B, Z, N) f32

    setup_csr<<<1, EE>>>(etv);
    init_x2<<<dim3(EE, BB), CT>>>(xa, etv);

    const dim3 cgrid(MM / CM, BB);
    const dim3 cblock(CT, CM);
    const dim3 vgrid(3, 17, BB);
    const size_t slice = (size_t)BB * ZZ * NN;

    for (int it = 0; it < NITER; ++it) {
        check_kernel<<<cgrid, cblock>>>(shift, cnw, it);
        if (it < NITER - 1)
            var_kernel<true><<<vgrid, 128>>>(xa, out + (size_t)it * slice);
        else
            var_kernel<false><<<vgrid, 128>>>(xa, out + (size_t)it * slice);
    }
}